// round 10
// baseline (speedup 1.0000x reference)
#include <cuda_runtime.h>
#include <cuda_fp16.h>
#include <math.h>
#include <stdint.h>

// ---------------------------------------------------------------------------
// Decomposable-Attention NLI forward. mma.sync fp16 hi/lo-split (3 products)
// GEMMs with PRODUCT-MAJOR mma ordering (16-deep independent HMMA streams),
// ldmatrix fragments, 3-stage single-sync cp.async pipeline.
// B=32, L=256, D=1024, FF=2048.
// ---------------------------------------------------------------------------

// fp16 scratch offsets (elements)
#define O_PH_H 0L
#define O_PH_L 8388608L
#define O_HH_H 16777216L
#define O_HH_L 25165824L
#define O_FP_H 33554432L
#define O_FP_L 41943040L
#define O_FH_H 50331648L
#define O_FH_L 58720256L
#define O_PT_H 67108864L
#define O_PT_L 75497472L
#define O_HT_H 83886080L
#define O_HT_L 92274688L
#define O_BE_H 100663296L
#define O_BE_L 109051904L
#define O_AL_H 117440512L
#define O_AL_L 125829120L
#define O_WF_H 134217728L
#define O_WF_L 135266304L
#define O_WG_H 136314880L
#define O_WG_L 140509184L
#define O_AT_H 144703488L
#define O_AT_L 146800640L
#define O_TT_H 148897792L
#define O_TT_L 150994944L
#define BF_TOTAL 153092096L
#define OF_E  0L
#define OF_S1 2097152L
#define OF_S2 2162688L
#define OF_A1 2228224L
#define OF_A2 2293760L
#define F32_TOTAL 2359296L

__device__ __align__(1024) __half g_hf[BF_TOTAL];
__device__ __align__(1024) float g_f32[F32_TOTAL];

// stage layout (bytes): Ah 16K | Al 16K | Bh 16K | Bl 16K = 64KB; 3 stages
#define ST_AL 16384
#define ST_BH 32768
#define ST_BL 49152
#define ST_SZ 65536

__device__ __forceinline__ uint32_t smem_u32(const void* p) {
    uint32_t a;
    asm("{ .reg .u64 t; cvta.to.shared.u64 t, %1; cvt.u32.u64 %0, t; }" : "=r"(a) : "l"(p));
    return a;
}
__device__ __forceinline__ void split1(float v, __half& h, __half& l) {
    h = __float2half_rn(v);
    l = __float2half_rn(v - __half2float(h));
}
__device__ __forceinline__ uint32_t pk(__half a, __half b) {
    return (uint32_t)__half_as_ushort(a) | ((uint32_t)__half_as_ushort(b) << 16);
}
__device__ __forceinline__ void mma_f16(float* c, const uint32_t* a, const uint32_t* b) {
    asm volatile(
        "mma.sync.aligned.m16n8k16.row.col.f32.f16.f16.f32 "
        "{%0,%1,%2,%3},{%4,%5,%6,%7},{%8,%9},{%0,%1,%2,%3};\n"
        : "+f"(c[0]), "+f"(c[1]), "+f"(c[2]), "+f"(c[3])
        : "r"(a[0]), "r"(a[1]), "r"(a[2]), "r"(a[3]), "r"(b[0]), "r"(b[1]));
}
__device__ __forceinline__ void ldsm4(uint32_t* r, uint32_t addr) {
    asm volatile("ldmatrix.sync.aligned.m8n8.x4.shared.b16 {%0,%1,%2,%3}, [%4];"
                 : "=r"(r[0]), "=r"(r[1]), "=r"(r[2]), "=r"(r[3]) : "r"(addr));
}

// cp.async a 128-row x 64-fp16(128B) SW128 tile; 256 threads
__device__ __forceinline__ void ld_sw128(uint32_t sb, const __half* g, long ld, int t) {
#pragma unroll
    for (int i = 0; i < 4; i++) {
        const int idx = t + i * 256;
        const int r = idx >> 3, c = idx & 7;
        uint32_t dst = sb + r * 128 + ((c ^ (r & 7)) << 4);
        asm volatile("cp.async.cg.shared.global [%0], [%1], 16;"
                     :: "r"(dst), "l"(g + (long)r * ld + c * 8) : "memory");
    }
}

// warp compute over one K64 stage. warp tile 64(m) x 32(n); 3 split products,
// PRODUCT-MAJOR issue order: 16 independent mma per pass, acc reuse distance 16.
__device__ __forceinline__ void wcompute(uint32_t Ab, uint32_t Bb, float acc[4][4][4],
                                         int wm, int wn, int lane) {
    const int lm = lane & 7, mat = lane >> 3;
    const int rsel = (mat & 1) * 8 + lm;   // row within 16-row frag
    const int csel = mat >> 1;             // 16B chunk offset (0/1)
#pragma unroll
    for (int s = 0; s < 4; s++) {
        const int ch = 2 * s + csel;
        uint32_t ah[4][4], al[4][4], bh[4][2], bl[4][2];
#pragma unroll
        for (int nfp = 0; nfp < 2; nfp++) {
            const int rn = wn * 32 + nfp * 16 + rsel;
            const uint32_t off = rn * 128 + ((ch ^ (rn & 7)) << 4);
            uint32_t q[4];
            ldsm4(q, Bb + off);
            bh[nfp * 2][0] = q[0]; bh[nfp * 2 + 1][0] = q[1];
            bh[nfp * 2][1] = q[2]; bh[nfp * 2 + 1][1] = q[3];
            ldsm4(q, Bb + 16384 + off);
            bl[nfp * 2][0] = q[0]; bl[nfp * 2 + 1][0] = q[1];
            bl[nfp * 2][1] = q[2]; bl[nfp * 2 + 1][1] = q[3];
        }
#pragma unroll
        for (int mf = 0; mf < 4; mf++) {
            const int rm = wm * 64 + mf * 16 + rsel;
            const uint32_t off = rm * 128 + ((ch ^ (rm & 7)) << 4);
            ldsm4(ah[mf], Ab + off);
            ldsm4(al[mf], Ab + ST_AL + off);
        }
        // pass 1: Ah @ Bh  (16 independent mma)
#pragma unroll
        for (int mf = 0; mf < 4; mf++)
#pragma unroll
            for (int nf = 0; nf < 4; nf++) mma_f16(acc[mf][nf], ah[mf], bh[nf]);
        // pass 2: Ah @ Bl
#pragma unroll
        for (int mf = 0; mf < 4; mf++)
#pragma unroll
            for (int nf = 0; nf < 4; nf++) mma_f16(acc[mf][nf], ah[mf], bl[nf]);
        // pass 3: Al @ Bh
#pragma unroll
        for (int mf = 0; mf < 4; mf++)
#pragma unroll
            for (int nf = 0; nf < 4; nf++) mma_f16(acc[mf][nf], al[mf], bh[nf]);
    }
}

// ---------------------------------------------------------------------------
// D = A @ B^T. A[m][k], B[n][k] fp16 h/l row-major. Block tile 128x128,
// 256 threads (8 warps 2x4), 3-stage single-sync pipeline.
// EPI: 0 = fp32 store; 1 = hi/lo pack store; 2 = tanh + pack store.
// ---------------------------------------------------------------------------
template <int EPI>
__global__ __launch_bounds__(256, 1) void mm(
    const __half* __restrict__ Ah, const __half* __restrict__ Al, long lda, long sA,
    const __half* __restrict__ Bh, const __half* __restrict__ Bl, long ldb, long sB,
    float* __restrict__ Cf, long ldc, long sC,
    __half* __restrict__ Oh, __half* __restrict__ Ol, long ldo, long sO, int K)
{
    extern __shared__ __align__(16) char dsm[];
    const uint32_t base = smem_u32(dsm);
    const int t = threadIdx.x, lane = t & 31, wid = t >> 5;
    const int wm = wid >> 2, wn = wid & 3;
    const int bm = blockIdx.y * 128, bn = blockIdx.x * 128, z = blockIdx.z;

    const __half* Azh = Ah + z * sA + (long)bm * lda;
    const __half* Azl = Al + z * sA + (long)bm * lda;
    const __half* Bzh = Bh + z * sB + (long)bn * ldb;
    const __half* Bzl = Bl + z * sB + (long)bn * ldb;
    const int ns = K >> 6;

    float acc[4][4][4];
#pragma unroll
    for (int i = 0; i < 4; i++)
#pragma unroll
        for (int j = 0; j < 4; j++)
#pragma unroll
            for (int q = 0; q < 4; q++) acc[i][j][q] = 0.f;

    auto issue = [&](int j, int buf) {
        const uint32_t sb = base + buf * ST_SZ;
        const long ko = (long)j << 6;
        ld_sw128(sb,         Azh + ko, lda, t);
        ld_sw128(sb + ST_AL, Azl + ko, lda, t);
        ld_sw128(sb + ST_BH, Bzh + ko, ldb, t);
        ld_sw128(sb + ST_BL, Bzl + ko, ldb, t);
        asm volatile("cp.async.commit_group;" ::: "memory");
    };

    issue(0, 0);
    issue(1, 1);
    for (int j = 0; j < ns; j++) {
        if (j + 1 < ns) asm volatile("cp.async.wait_group 1;" ::: "memory");
        else            asm volatile("cp.async.wait_group 0;" ::: "memory");
        __syncthreads();
        const uint32_t sb = base + (j % 3) * ST_SZ;
        wcompute(sb, sb + ST_BH, acc, wm, wn, lane);
        if (j + 2 < ns) issue(j + 2, (j + 2) % 3);
    }

    const int r = lane >> 2, c2 = (lane & 3) * 2;
#pragma unroll
    for (int mf = 0; mf < 4; mf++)
#pragma unroll
        for (int nf = 0; nf < 4; nf++) {
            const int row = bm + wm * 64 + mf * 16 + r;
            const int col = bn + wn * 32 + nf * 8 + c2;
            float v0 = acc[mf][nf][0], v1 = acc[mf][nf][1];
            float v2 = acc[mf][nf][2], v3 = acc[mf][nf][3];
            if (EPI == 2) { v0 = tanhf(v0); v1 = tanhf(v1); v2 = tanhf(v2); v3 = tanhf(v3); }
            if (EPI == 0) {
                *(float2*)&Cf[z * sC + (long)row * ldc + col] = make_float2(v0, v1);
                *(float2*)&Cf[z * sC + (long)(row + 8) * ldc + col] = make_float2(v2, v3);
            } else {
                __half h0, l0, h1, l1;
                split1(v0, h0, l0); split1(v1, h1, l1);
                const long o0 = z * sO + (long)row * ldo + col;
                *(uint32_t*)&Oh[o0] = pk(h0, h1);
                *(uint32_t*)&Ol[o0] = pk(l0, l1);
                split1(v2, h0, l0); split1(v3, h1, l1);
                const long o1 = z * sO + (long)(row + 8) * ldo + col;
                *(uint32_t*)&Oh[o1] = pk(h0, h1);
                *(uint32_t*)&Ol[o1] = pk(l0, l1);
            }
        }
}

// ---------------------------------------------------------------------------
// Fused compare: S[z,n] = sum_{p<256} tanh( concat(X1,X2)[z,p,:] @ W[:,n] )
// Two 128-row m-tiles sequential in-kernel; K=2048 (X1 k<1024, X2 k>=1024).
// ---------------------------------------------------------------------------
__global__ __launch_bounds__(256, 1) void mm_compare(
    const __half* __restrict__ X1h, const __half* __restrict__ X1l,
    const __half* __restrict__ X2h, const __half* __restrict__ X2l,
    const __half* __restrict__ Wh,  const __half* __restrict__ Wl,
    float* __restrict__ S)
{
    extern __shared__ __align__(16) char dsm[];
    __shared__ float red[2][128];
    const uint32_t base = smem_u32(dsm);
    const int t = threadIdx.x, lane = t & 31, wid = t >> 5;
    const int wm = wid >> 2, wn = wid & 3;
    const int bn = blockIdx.x * 128, z = blockIdx.z;

    const __half* Wbh = Wh + (long)bn * 2048;
    const __half* Wbl = Wl + (long)bn * 2048;

    float csum[4][2];
#pragma unroll
    for (int nf = 0; nf < 4; nf++) { csum[nf][0] = 0.f; csum[nf][1] = 0.f; }

    for (int mt = 0; mt < 2; mt++) {
        float acc[4][4][4];
#pragma unroll
        for (int i = 0; i < 4; i++)
#pragma unroll
            for (int j = 0; j < 4; j++)
#pragma unroll
                for (int q = 0; q < 4; q++) acc[i][j][q] = 0.f;

        auto issue = [&](int j, int buf) {
            const uint32_t sb = base + buf * ST_SZ;
            const __half* axh;
            const __half* axl;
            const long ro = (long)z * 262144 + (long)mt * 131072;
            if (j < 16) {
                axh = X1h + ro + ((long)j << 6);
                axl = X1l + ro + ((long)j << 6);
            } else {
                axh = X2h + ro + ((long)(j - 16) << 6);
                axl = X2l + ro + ((long)(j - 16) << 6);
            }
            ld_sw128(sb,         axh, 1024, t);
            ld_sw128(sb + ST_AL, axl, 1024, t);
            ld_sw128(sb + ST_BH, Wbh + ((long)j << 6), 2048, t);
            ld_sw128(sb + ST_BL, Wbl + ((long)j << 6), 2048, t);
            asm volatile("cp.async.commit_group;" ::: "memory");
        };

        issue(0, 0);
        issue(1, 1);
        for (int j = 0; j < 32; j++) {
            if (j + 1 < 32) asm volatile("cp.async.wait_group 1;" ::: "memory");
            else            asm volatile("cp.async.wait_group 0;" ::: "memory");
            __syncthreads();
            const uint32_t sb = base + (j % 3) * ST_SZ;
            wcompute(sb, sb + ST_BH, acc, wm, wn, lane);
            if (j + 2 < 32) issue(j + 2, (j + 2) % 3);
        }
#pragma unroll
        for (int mf = 0; mf < 4; mf++)
#pragma unroll
            for (int nf = 0; nf < 4; nf++) {
                csum[nf][0] += tanhf(acc[mf][nf][0]) + tanhf(acc[mf][nf][2]);
                csum[nf][1] += tanhf(acc[mf][nf][1]) + tanhf(acc[mf][nf][3]);
            }
        __syncthreads();  // all warps done with buffers before next m-tile refill
    }

#pragma unroll
    for (int off = 4; off <= 16; off <<= 1)
#pragma unroll
        for (int nf = 0; nf < 4; nf++) {
            csum[nf][0] += __shfl_xor_sync(0xffffffffu, csum[nf][0], off);
            csum[nf][1] += __shfl_xor_sync(0xffffffffu, csum[nf][1], off);
        }
    if (lane < 4) {
#pragma unroll
        for (int nf = 0; nf < 4; nf++) {
            red[wm][wn * 32 + nf * 8 + 2 * lane + 0] = csum[nf][0];
            red[wm][wn * 32 + nf * 8 + 2 * lane + 1] = csum[nf][1];
        }
    }
    __syncthreads();
    if (t < 128)
        S[(long)z * 2048 + bn + t] = red[0][t] + red[1][t];
}

// fp32 row-major -> elementwise fp16 hi/lo (same layout); two tensors via grid.y
__global__ __launch_bounds__(256) void pack_nat2(
    const float* __restrict__ X0, const float* __restrict__ X1,
    __half* __restrict__ H0, __half* __restrict__ L0,
    __half* __restrict__ H1, __half* __restrict__ L1, long n4)
{
    const long i = (long)blockIdx.x * 256 + threadIdx.x;
    if (i >= n4) return;
    const float* X = blockIdx.y ? X1 : X0;
    __half* H = blockIdx.y ? H1 : H0;
    __half* L = blockIdx.y ? L1 : L0;
    float4 v = ((const float4*)X)[i];
    __half h[4], l[4];
    split1(v.x, h[0], l[0]); split1(v.y, h[1], l[1]);
    split1(v.z, h[2], l[2]); split1(v.w, h[3], l[3]);
    ((uint2*)H)[i] = make_uint2(pk(h[0], h[1]), pk(h[2], h[3]));
    ((uint2*)L)[i] = make_uint2(pk(l[0], l[1]), pk(l[2], l[3]));
}

// fp32 [Z][R][C] -> fp16 hi/lo [Z][C][R]
__global__ __launch_bounds__(256) void pack_T(
    const float* __restrict__ X, __half* __restrict__ H,
    __half* __restrict__ L, int R, int C)
{
    __shared__ float tile[32][33];
    const int c0 = blockIdx.x * 32, r0 = blockIdx.y * 32;
    const int tx = threadIdx.x & 31, ty = threadIdx.x >> 5;
    const long zoff = (long)blockIdx.z * R * C;
#pragma unroll
    for (int i = 0; i < 4; i++)
        tile[ty + i * 8][tx] = X[zoff + (long)(r0 + ty + i * 8) * C + c0 + tx];
    __syncthreads();
#pragma unroll
    for (int i = 0; i < 4; i++) {
        const int c = ty + i * 8;
        __half h, l;
        split1(tile[tx][c], h, l);
        H[zoff + (long)(c0 + c) * R + r0 + tx] = h;
        L[zoff + (long)(c0 + c) * R + r0 + tx] = l;
    }
}

// softmax over 256 cols; writes attn [b][p][h] and attn^T [b][h][p] hi/lo
__global__ void softmax_pack(
    const float* __restrict__ E,
    __half* __restrict__ ATh, __half* __restrict__ ATl,
    __half* __restrict__ TTh, __half* __restrict__ TTl)
{
    __shared__ float sm[8][257];
    const int b = blockIdx.x >> 5;
    const int p0 = (blockIdx.x & 31) << 3;
    const int lane = threadIdx.x, ty = threadIdx.y;
    const float* row = E + ((long)b * 256 + p0 + ty) * 256;
    float v[8];
    float mx = -1e30f;
#pragma unroll
    for (int i = 0; i < 8; i++) { v[i] = row[i * 32 + lane]; mx = fmaxf(mx, v[i]); }
#pragma unroll
    for (int o = 16; o; o >>= 1) mx = fmaxf(mx, __shfl_xor_sync(0xffffffffu, mx, o));
    float s = 0.f;
#pragma unroll
    for (int i = 0; i < 8; i++) { v[i] = expf(v[i] - mx); s += v[i]; }
#pragma unroll
    for (int o = 16; o; o >>= 1) s += __shfl_xor_sync(0xffffffffu, s, o);
    const float inv = 1.0f / s;
#pragma unroll
    for (int i = 0; i < 8; i++) sm[ty][i * 32 + lane] = v[i] * inv;
    __syncthreads();
    const int t = ty * 32 + lane;
    {
        const int pr = t >> 5, c0 = (t & 31) << 3;
        uint32_t hw[4], lw[4];
#pragma unroll
        for (int q = 0; q < 4; q++) {
            __half h0, l0, h1, l1;
            split1(sm[pr][c0 + 2 * q], h0, l0); split1(sm[pr][c0 + 2 * q + 1], h1, l1);
            hw[q] = pk(h0, h1); lw[q] = pk(l0, l1);
        }
        const long o = ((long)b * 256 + p0 + pr) * 256 + c0;
        *(uint4*)&ATh[o] = make_uint4(hw[0], hw[1], hw[2], hw[3]);
        *(uint4*)&ATl[o] = make_uint4(lw[0], lw[1], lw[2], lw[3]);
    }
    {
        uint32_t hw[4], lw[4];
#pragma unroll
        for (int q = 0; q < 4; q++) {
            __half h0, l0, h1, l1;
            split1(sm[2 * q][t], h0, l0); split1(sm[2 * q + 1][t], h1, l1);
            hw[q] = pk(h0, h1); lw[q] = pk(l0, l1);
        }
        const long o = ((long)b * 256 + t) * 256 + p0;
        *(uint4*)&TTh[o] = make_uint4(hw[0], hw[1], hw[2], hw[3]);
        *(uint4*)&TTl[o] = make_uint4(lw[0], lw[1], lw[2], lw[3]);
    }
}

__global__ __launch_bounds__(128) void mlp_layer_kernel(
    const float* __restrict__ A1, const float* __restrict__ A2, int ksplit,
    const float* __restrict__ W, const float* __restrict__ bias,
    float* __restrict__ out, int N, int K, int do_tanh)
{
    const int n = blockIdx.x * 128 + threadIdx.x;
    const int m0 = blockIdx.y * 8;
    __shared__ float As[8][129];
    float acc[8];
#pragma unroll
    for (int i = 0; i < 8; i++) acc[i] = 0.f;
    for (int k0 = 0; k0 < K; k0 += 128) {
#pragma unroll
        for (int i = 0; i < 8; i++) {
            const int k = k0 + threadIdx.x;
            As[i][threadIdx.x] = (k < ksplit)
                ? A1[(long)(m0 + i) * ksplit + k]
                : A2[(long)(m0 + i) * ksplit + (k - ksplit)];
        }
        __syncthreads();
        for (int kk = 0; kk < 128; kk++) {
            const float wv = W[(long)(k0 + kk) * N + n];
#pragma unroll
            for (int i = 0; i < 8; i++) acc[i] += As[i][kk] * wv;
        }
        __syncthreads();
    }
    const float bb = bias[n];
#pragma unroll
    for (int i = 0; i < 8; i++) {
        float r = acc[i] + bb;
        out[(long)(m0 + i) * N + n] = do_tanh ? tanhf(r) : r;
    }
}

__global__ void final_layer_kernel(
    const float* __restrict__ A, const float* __restrict__ W3,
    const float* __restrict__ b3, float* __restrict__ out)
{
    const int m = blockIdx.x / 3, n = blockIdx.x % 3, lane = threadIdx.x;
    float s = 0.f;
    for (int k = lane; k < 2048; k += 32)
        s += A[(long)m * 2048 + k] * W3[(long)k * 3 + n];
#pragma unroll
    for (int o = 16; o; o >>= 1) s += __shfl_xor_sync(0xffffffffu, s, o);
    if (lane == 0) out[m * 3 + n] = s + b3[n];
}

extern "C" void kernel_launch(void* const* d_in, const int* in_sizes, int n_in,
                              void* d_out, int out_size)
{
    const float* P   = (const float*)d_in[0];
    const float* Hy  = (const float*)d_in[1];
    const float* W_F = (const float*)d_in[2];
    const float* W_G = (const float*)d_in[3];
    const float* W1  = (const float*)d_in[4];
    const float* b1  = (const float*)d_in[5];
    const float* W2  = (const float*)d_in[6];
    const float* b2  = (const float*)d_in[7];
    const float* W3  = (const float*)d_in[8];
    const float* b3  = (const float*)d_in[9];
    float* out = (float*)d_out;

    __half* hf = nullptr;
    float* f32 = nullptr;
    cudaGetSymbolAddress((void**)&hf, g_hf);
    cudaGetSymbolAddress((void**)&f32, g_f32);

    const int SM = 3 * ST_SZ;  // 192KB dynamic
    cudaFuncSetAttribute(mm<0>, cudaFuncAttributeMaxDynamicSharedMemorySize, SM);
    cudaFuncSetAttribute(mm<1>, cudaFuncAttributeMaxDynamicSharedMemorySize, SM);
    cudaFuncSetAttribute(mm<2>, cudaFuncAttributeMaxDynamicSharedMemorySize, SM);
    cudaFuncSetAttribute(mm_compare, cudaFuncAttributeMaxDynamicSharedMemorySize, SM);

    float* E  = f32 + OF_E;
    float* S1 = f32 + OF_S1;
    float* S2 = f32 + OF_S2;
    float* a1 = f32 + OF_A1;
    float* a2 = f32 + OF_A2;

    // launch order: proj GEMM at index 3 (rounds 5/9 show ncu profiles index 3)
    pack_nat2<<<dim3(8192, 2), 256>>>(P, Hy, hf + O_PH_H, hf + O_PH_L,
                                      hf + O_HH_H, hf + O_HH_L, 2097152);       // 0
    pack_T<<<dim3(32, 32, 1), 256>>>(W_F, hf + O_WF_H, hf + O_WF_L, 1024, 1024); // 1
    pack_T<<<dim3(64, 64, 1), 256>>>(W_G, hf + O_WG_H, hf + O_WG_L, 2048, 2048); // 2

    // projections: Fp/Fh = tanh(X @ W_F). A [8192][1024], B = W_F^T [1024][1024]
    mm<2><<<dim3(8, 64, 1), 256, SM>>>(                                          // 3 <- ncu
        hf + O_PH_H, hf + O_PH_L, 1024, 0, hf + O_WF_H, hf + O_WF_L, 1024, 0,
        nullptr, 0, 0, hf + O_FP_H, hf + O_FP_L, 1024, 0, 1024);
    mm<2><<<dim3(8, 64, 1), 256, SM>>>(                                          // 4
        hf + O_HH_H, hf + O_HH_L, 1024, 0, hf + O_WF_H, hf + O_WF_L, 1024, 0,
        nullptr, 0, 0, hf + O_FH_H, hf + O_FH_L, 1024, 0, 1024);

    pack_T<<<dim3(32, 8, 32), 256>>>(P,  hf + O_PT_H, hf + O_PT_L, 256, 1024);   // 5
    pack_T<<<dim3(32, 8, 32), 256>>>(Hy, hf + O_HT_H, hf + O_HT_L, 256, 1024);   // 6

    // E[b] = Fp[b] @ Fh[b]^T
    mm<0><<<dim3(2, 2, 32), 256, SM>>>(
        hf + O_FP_H, hf + O_FP_L, 1024, 262144, hf + O_FH_H, hf + O_FH_L, 1024, 262144,
        E, 256, 65536, nullptr, nullptr, 0, 0, 1024);

    softmax_pack<<<1024, dim3(32, 8)>>>(E, hf + O_AT_H, hf + O_AT_L, hf + O_TT_H, hf + O_TT_L);

    // betas = attn @ H (B = H^T) ; alphas = attn^T @ P (B = P^T)
    mm<1><<<dim3(8, 2, 32), 256, SM>>>(
        hf + O_AT_H, hf + O_AT_L, 256, 65536, hf + O_HT_H, hf + O_HT_L, 256, 262144,
        nullptr, 0, 0, hf + O_BE_H, hf + O_BE_L, 1024, 262144, 256);
    mm<1><<<dim3(8, 2, 32), 256, SM>>>(
        hf + O_TT_H, hf + O_TT_L, 256, 65536, hf + O_PT_H, hf + O_PT_L, 256, 262144,
        nullptr, 0, 0, hf + O_AL_H, hf + O_AL_L, 1024, 262144, 256);

    // compare (fused GEMM + tanh + sequence-sum)
    mm_compare<<<dim3(16, 1, 32), 256, SM>>>(
        hf + O_PH_H, hf + O_PH_L, hf + O_BE_H, hf + O_BE_L, hf + O_WG_H, hf + O_WG_L, S1);
    mm_compare<<<dim3(16, 1, 32), 256, SM>>>(
        hf + O_HH_H, hf + O_HH_L, hf + O_AL_H, hf + O_AL_L, hf + O_WG_H, hf + O_WG_L, S2);

    // classifier
    mlp_layer_kernel<<<dim3(16, 4), 128>>>(S1, S2, 2048, W1, b1, a1, 2048, 4096, 1);
    mlp_layer_kernel<<<dim3(16, 4), 128>>>(a1, a1, 2048, W2, b2, a2, 2048, 2048, 1);
    final_layer_kernel<<<96, 32>>>(a2, W3, b3, out);
}

// round 11
// speedup vs baseline: 1.0304x; 1.0304x over previous
#include <cuda_runtime.h>
#include <cuda_fp16.h>
#include <math.h>
#include <stdint.h>

// ---------------------------------------------------------------------------
// Decomposable-Attention NLI forward. mma.sync fp16 hi/lo-split (3 products)
// GEMMs. 128x128 tile, 512 threads (16 warps, 32x32 warp tiles) for 4
// warps/SMSP latency hiding. ldmatrix + 3-stage single-sync cp.async ring.
// B=32, L=256, D=1024, FF=2048.
// ---------------------------------------------------------------------------

// fp16 scratch offsets (elements)
#define O_PH_H 0L
#define O_PH_L 8388608L
#define O_HH_H 16777216L
#define O_HH_L 25165824L
#define O_FP_H 33554432L
#define O_FP_L 41943040L
#define O_FH_H 50331648L
#define O_FH_L 58720256L
#define O_PT_H 67108864L
#define O_PT_L 75497472L
#define O_HT_H 83886080L
#define O_HT_L 92274688L
#define O_BE_H 100663296L
#define O_BE_L 109051904L
#define O_AL_H 117440512L
#define O_AL_L 125829120L
#define O_WF_H 134217728L
#define O_WF_L 135266304L
#define O_WG_H 136314880L
#define O_WG_L 140509184L
#define O_AT_H 144703488L
#define O_AT_L 146800640L
#define O_TT_H 148897792L
#define O_TT_L 150994944L
#define BF_TOTAL 153092096L
#define OF_E  0L
#define OF_S1 2097152L
#define OF_S2 2162688L
#define OF_A1 2228224L
#define OF_A2 2293760L
#define F32_TOTAL 2359296L

__device__ __align__(1024) __half g_hf[BF_TOTAL];
__device__ __align__(1024) float g_f32[F32_TOTAL];

// stage layout (bytes): Ah 16K | Al 16K | Bh 16K | Bl 16K = 64KB; 3 stages
#define ST_AL 16384
#define ST_BH 32768
#define ST_BL 49152
#define ST_SZ 65536

__device__ __forceinline__ uint32_t smem_u32(const void* p) {
    uint32_t a;
    asm("{ .reg .u64 t; cvta.to.shared.u64 t, %1; cvt.u32.u64 %0, t; }" : "=r"(a) : "l"(p));
    return a;
}
__device__ __forceinline__ void split1(float v, __half& h, __half& l) {
    h = __float2half_rn(v);
    l = __float2half_rn(v - __half2float(h));
}
__device__ __forceinline__ uint32_t pk(__half a, __half b) {
    return (uint32_t)__half_as_ushort(a) | ((uint32_t)__half_as_ushort(b) << 16);
}
__device__ __forceinline__ void mma_f16(float* c, const uint32_t* a, const uint32_t* b) {
    asm volatile(
        "mma.sync.aligned.m16n8k16.row.col.f32.f16.f16.f32 "
        "{%0,%1,%2,%3},{%4,%5,%6,%7},{%8,%9},{%0,%1,%2,%3};\n"
        : "+f"(c[0]), "+f"(c[1]), "+f"(c[2]), "+f"(c[3])
        : "r"(a[0]), "r"(a[1]), "r"(a[2]), "r"(a[3]), "r"(b[0]), "r"(b[1]));
}
__device__ __forceinline__ void ldsm4(uint32_t* r, uint32_t addr) {
    asm volatile("ldmatrix.sync.aligned.m8n8.x4.shared.b16 {%0,%1,%2,%3}, [%4];"
                 : "=r"(r[0]), "=r"(r[1]), "=r"(r[2]), "=r"(r[3]) : "r"(addr));
}

// cp.async a 128-row x 64-fp16(128B) SW128 tile; 512 threads
__device__ __forceinline__ void ld_sw128(uint32_t sb, const __half* g, long ld, int t) {
#pragma unroll
    for (int i = 0; i < 2; i++) {
        const int idx = t + i * 512;
        const int r = idx >> 3, c = idx & 7;
        uint32_t dst = sb + r * 128 + ((c ^ (r & 7)) << 4);
        asm volatile("cp.async.cg.shared.global [%0], [%1], 16;"
                     :: "r"(dst), "l"(g + (long)r * ld + c * 8) : "memory");
    }
}

// warp compute over one K64 stage. warp tile 32(m) x 32(n); 3 split products,
// product-major issue order (8 independent mma per pass).
__device__ __forceinline__ void wcompute(uint32_t Ab, uint32_t Bb, float acc[2][4][4],
                                         int wm, int wn, int lane) {
    const int lm = lane & 7, mat = lane >> 3;
    const int rsel = (mat & 1) * 8 + lm;   // row within 16-row frag
    const int csel = mat >> 1;             // 16B chunk offset (0/1)
#pragma unroll
    for (int s = 0; s < 4; s++) {
        const int ch = 2 * s + csel;
        uint32_t ah[2][4], al[2][4], bh[4][2], bl[4][2];
#pragma unroll
        for (int nfp = 0; nfp < 2; nfp++) {
            const int rn = wn * 32 + nfp * 16 + rsel;
            const uint32_t off = rn * 128 + ((ch ^ (rn & 7)) << 4);
            uint32_t q[4];
            ldsm4(q, Bb + off);
            bh[nfp * 2][0] = q[0]; bh[nfp * 2 + 1][0] = q[1];
            bh[nfp * 2][1] = q[2]; bh[nfp * 2 + 1][1] = q[3];
            ldsm4(q, Bb + 16384 + off);
            bl[nfp * 2][0] = q[0]; bl[nfp * 2 + 1][0] = q[1];
            bl[nfp * 2][1] = q[2]; bl[nfp * 2 + 1][1] = q[3];
        }
#pragma unroll
        for (int mf = 0; mf < 2; mf++) {
            const int rm = wm * 32 + mf * 16 + rsel;
            const uint32_t off = rm * 128 + ((ch ^ (rm & 7)) << 4);
            ldsm4(ah[mf], Ab + off);
            ldsm4(al[mf], Ab + ST_AL + off);
        }
        // pass 1: Ah @ Bh (8 independent mma)
#pragma unroll
        for (int mf = 0; mf < 2; mf++)
#pragma unroll
            for (int nf = 0; nf < 4; nf++) mma_f16(acc[mf][nf], ah[mf], bh[nf]);
        // pass 2: Ah @ Bl
#pragma unroll
        for (int mf = 0; mf < 2; mf++)
#pragma unroll
            for (int nf = 0; nf < 4; nf++) mma_f16(acc[mf][nf], ah[mf], bl[nf]);
        // pass 3: Al @ Bh
#pragma unroll
        for (int mf = 0; mf < 2; mf++)
#pragma unroll
            for (int nf = 0; nf < 4; nf++) mma_f16(acc[mf][nf], al[mf], bh[nf]);
    }
}

// ---------------------------------------------------------------------------
// D = A @ B^T. A[m][k], B[n][k] fp16 h/l row-major. Block tile 128x128,
// 512 threads (16 warps 4x4), 3-stage single-sync pipeline.
// EPI: 0 = fp32 store; 1 = hi/lo pack store; 2 = tanh + pack store.
// ---------------------------------------------------------------------------
template <int EPI>
__global__ __launch_bounds__(512, 1) void mm(
    const __half* __restrict__ Ah, const __half* __restrict__ Al, long lda, long sA,
    const __half* __restrict__ Bh, const __half* __restrict__ Bl, long ldb, long sB,
    float* __restrict__ Cf, long ldc, long sC,
    __half* __restrict__ Oh, __half* __restrict__ Ol, long ldo, long sO, int K)
{
    extern __shared__ __align__(16) char dsm[];
    const uint32_t base = smem_u32(dsm);
    const int t = threadIdx.x, lane = t & 31, wid = t >> 5;
    const int wm = wid >> 2, wn = wid & 3;
    const int bm = blockIdx.y * 128, bn = blockIdx.x * 128, z = blockIdx.z;

    const __half* Azh = Ah + z * sA + (long)bm * lda;
    const __half* Azl = Al + z * sA + (long)bm * lda;
    const __half* Bzh = Bh + z * sB + (long)bn * ldb;
    const __half* Bzl = Bl + z * sB + (long)bn * ldb;
    const int ns = K >> 6;

    float acc[2][4][4];
#pragma unroll
    for (int i = 0; i < 2; i++)
#pragma unroll
        for (int j = 0; j < 4; j++)
#pragma unroll
            for (int q = 0; q < 4; q++) acc[i][j][q] = 0.f;

    auto issue = [&](int j, int buf) {
        const uint32_t sb = base + buf * ST_SZ;
        const long ko = (long)j << 6;
        ld_sw128(sb,         Azh + ko, lda, t);
        ld_sw128(sb + ST_AL, Azl + ko, lda, t);
        ld_sw128(sb + ST_BH, Bzh + ko, ldb, t);
        ld_sw128(sb + ST_BL, Bzl + ko, ldb, t);
        asm volatile("cp.async.commit_group;" ::: "memory");
    };

    issue(0, 0);
    issue(1, 1);
    for (int j = 0; j < ns; j++) {
        if (j + 1 < ns) asm volatile("cp.async.wait_group 1;" ::: "memory");
        else            asm volatile("cp.async.wait_group 0;" ::: "memory");
        __syncthreads();
        const uint32_t sb = base + (j % 3) * ST_SZ;
        wcompute(sb, sb + ST_BH, acc, wm, wn, lane);
        if (j + 2 < ns) issue(j + 2, (j + 2) % 3);
    }

    const int r = lane >> 2, c2 = (lane & 3) * 2;
#pragma unroll
    for (int mf = 0; mf < 2; mf++)
#pragma unroll
        for (int nf = 0; nf < 4; nf++) {
            const int row = bm + wm * 32 + mf * 16 + r;
            const int col = bn + wn * 32 + nf * 8 + c2;
            float v0 = acc[mf][nf][0], v1 = acc[mf][nf][1];
            float v2 = acc[mf][nf][2], v3 = acc[mf][nf][3];
            if (EPI == 2) { v0 = tanhf(v0); v1 = tanhf(v1); v2 = tanhf(v2); v3 = tanhf(v3); }
            if (EPI == 0) {
                *(float2*)&Cf[z * sC + (long)row * ldc + col] = make_float2(v0, v1);
                *(float2*)&Cf[z * sC + (long)(row + 8) * ldc + col] = make_float2(v2, v3);
            } else {
                __half h0, l0, h1, l1;
                split1(v0, h0, l0); split1(v1, h1, l1);
                const long o0 = z * sO + (long)row * ldo + col;
                *(uint32_t*)&Oh[o0] = pk(h0, h1);
                *(uint32_t*)&Ol[o0] = pk(l0, l1);
                split1(v2, h0, l0); split1(v3, h1, l1);
                const long o1 = z * sO + (long)(row + 8) * ldo + col;
                *(uint32_t*)&Oh[o1] = pk(h0, h1);
                *(uint32_t*)&Ol[o1] = pk(l0, l1);
            }
        }
}

// ---------------------------------------------------------------------------
// Fused compare: S[z,n] = sum_{p<256} tanh( concat(X1,X2)[z,p,:] @ W[:,n] )
// Two 128-row m-tiles sequential in-kernel; K=2048 (X1 k<1024, X2 k>=1024).
// ---------------------------------------------------------------------------
__global__ __launch_bounds__(512, 1) void mm_compare(
    const __half* __restrict__ X1h, const __half* __restrict__ X1l,
    const __half* __restrict__ X2h, const __half* __restrict__ X2l,
    const __half* __restrict__ Wh,  const __half* __restrict__ Wl,
    float* __restrict__ S)
{
    extern __shared__ __align__(16) char dsm[];
    __shared__ float red[4][128];
    const uint32_t base = smem_u32(dsm);
    const int t = threadIdx.x, lane = t & 31, wid = t >> 5;
    const int wm = wid >> 2, wn = wid & 3;
    const int bn = blockIdx.x * 128, z = blockIdx.z;

    const __half* Wbh = Wh + (long)bn * 2048;
    const __half* Wbl = Wl + (long)bn * 2048;

    float csum[4][2];
#pragma unroll
    for (int nf = 0; nf < 4; nf++) { csum[nf][0] = 0.f; csum[nf][1] = 0.f; }

    for (int mt = 0; mt < 2; mt++) {
        float acc[2][4][4];
#pragma unroll
        for (int i = 0; i < 2; i++)
#pragma unroll
            for (int j = 0; j < 4; j++)
#pragma unroll
                for (int q = 0; q < 4; q++) acc[i][j][q] = 0.f;

        auto issue = [&](int j, int buf) {
            const uint32_t sb = base + buf * ST_SZ;
            const __half* axh;
            const __half* axl;
            const long ro = (long)z * 262144 + (long)mt * 131072;
            if (j < 16) {
                axh = X1h + ro + ((long)j << 6);
                axl = X1l + ro + ((long)j << 6);
            } else {
                axh = X2h + ro + ((long)(j - 16) << 6);
                axl = X2l + ro + ((long)(j - 16) << 6);
            }
            ld_sw128(sb,         axh, 1024, t);
            ld_sw128(sb + ST_AL, axl, 1024, t);
            ld_sw128(sb + ST_BH, Wbh + ((long)j << 6), 2048, t);
            ld_sw128(sb + ST_BL, Wbl + ((long)j << 6), 2048, t);
            asm volatile("cp.async.commit_group;" ::: "memory");
        };

        issue(0, 0);
        issue(1, 1);
        for (int j = 0; j < 32; j++) {
            if (j + 1 < 32) asm volatile("cp.async.wait_group 1;" ::: "memory");
            else            asm volatile("cp.async.wait_group 0;" ::: "memory");
            __syncthreads();
            const uint32_t sb = base + (j % 3) * ST_SZ;
            wcompute(sb, sb + ST_BH, acc, wm, wn, lane);
            if (j + 2 < 32) issue(j + 2, (j + 2) % 3);
        }
#pragma unroll
        for (int mf = 0; mf < 2; mf++)
#pragma unroll
            for (int nf = 0; nf < 4; nf++) {
                csum[nf][0] += tanhf(acc[mf][nf][0]) + tanhf(acc[mf][nf][2]);
                csum[nf][1] += tanhf(acc[mf][nf][1]) + tanhf(acc[mf][nf][3]);
            }
        __syncthreads();  // all warps done with buffers before next m-tile refill
    }

    // sum the 8 row-groups within the warp (lanes sharing lane&3)
#pragma unroll
    for (int off = 4; off <= 16; off <<= 1)
#pragma unroll
        for (int nf = 0; nf < 4; nf++) {
            csum[nf][0] += __shfl_xor_sync(0xffffffffu, csum[nf][0], off);
            csum[nf][1] += __shfl_xor_sync(0xffffffffu, csum[nf][1], off);
        }
    if (lane < 4) {
#pragma unroll
        for (int nf = 0; nf < 4; nf++) {
            red[wm][wn * 32 + nf * 8 + 2 * lane + 0] = csum[nf][0];
            red[wm][wn * 32 + nf * 8 + 2 * lane + 1] = csum[nf][1];
        }
    }
    __syncthreads();
    if (t < 128)
        S[(long)z * 2048 + bn + t] = red[0][t] + red[1][t] + red[2][t] + red[3][t];
}

// fp32 row-major -> elementwise fp16 hi/lo (same layout); two tensors via grid.y
__global__ __launch_bounds__(256) void pack_nat2(
    const float* __restrict__ X0, const float* __restrict__ X1,
    __half* __restrict__ H0, __half* __restrict__ L0,
    __half* __restrict__ H1, __half* __restrict__ L1, long n4)
{
    const long i = (long)blockIdx.x * 256 + threadIdx.x;
    if (i >= n4) return;
    const float* X = blockIdx.y ? X1 : X0;
    __half* H = blockIdx.y ? H1 : H0;
    __half* L = blockIdx.y ? L1 : L0;
    float4 v = ((const float4*)X)[i];
    __half h[4], l[4];
    split1(v.x, h[0], l[0]); split1(v.y, h[1], l[1]);
    split1(v.z, h[2], l[2]); split1(v.w, h[3], l[3]);
    ((uint2*)H)[i] = make_uint2(pk(h[0], h[1]), pk(h[2], h[3]));
    ((uint2*)L)[i] = make_uint2(pk(l[0], l[1]), pk(l[2], l[3]));
}

// fp32 [Z][R][C] -> fp16 hi/lo [Z][C][R]
__global__ __launch_bounds__(256) void pack_T(
    const float* __restrict__ X, __half* __restrict__ H,
    __half* __restrict__ L, int R, int C)
{
    __shared__ float tile[32][33];
    const int c0 = blockIdx.x * 32, r0 = blockIdx.y * 32;
    const int tx = threadIdx.x & 31, ty = threadIdx.x >> 5;
    const long zoff = (long)blockIdx.z * R * C;
#pragma unroll
    for (int i = 0; i < 4; i++)
        tile[ty + i * 8][tx] = X[zoff + (long)(r0 + ty + i * 8) * C + c0 + tx];
    __syncthreads();
#pragma unroll
    for (int i = 0; i < 4; i++) {
        const int c = ty + i * 8;
        __half h, l;
        split1(tile[tx][c], h, l);
        H[zoff + (long)(c0 + c) * R + r0 + tx] = h;
        L[zoff + (long)(c0 + c) * R + r0 + tx] = l;
    }
}

// softmax over 256 cols; writes attn [b][p][h] and attn^T [b][h][p] hi/lo
__global__ void softmax_pack(
    const float* __restrict__ E,
    __half* __restrict__ ATh, __half* __restrict__ ATl,
    __half* __restrict__ TTh, __half* __restrict__ TTl)
{
    __shared__ float sm[8][257];
    const int b = blockIdx.x >> 5;
    const int p0 = (blockIdx.x & 31) << 3;
    const int lane = threadIdx.x, ty = threadIdx.y;
    const float* row = E + ((long)b * 256 + p0 + ty) * 256;
    float v[8];
    float mx = -1e30f;
#pragma unroll
    for (int i = 0; i < 8; i++) { v[i] = row[i * 32 + lane]; mx = fmaxf(mx, v[i]); }
#pragma unroll
    for (int o = 16; o; o >>= 1) mx = fmaxf(mx, __shfl_xor_sync(0xffffffffu, mx, o));
    float s = 0.f;
#pragma unroll
    for (int i = 0; i < 8; i++) { v[i] = expf(v[i] - mx); s += v[i]; }
#pragma unroll
    for (int o = 16; o; o >>= 1) s += __shfl_xor_sync(0xffffffffu, s, o);
    const float inv = 1.0f / s;
#pragma unroll
    for (int i = 0; i < 8; i++) sm[ty][i * 32 + lane] = v[i] * inv;
    __syncthreads();
    const int t = ty * 32 + lane;
    {
        const int pr = t >> 5, c0 = (t & 31) << 3;
        uint32_t hw[4], lw[4];
#pragma unroll
        for (int q = 0; q < 4; q++) {
            __half h0, l0, h1, l1;
            split1(sm[pr][c0 + 2 * q], h0, l0); split1(sm[pr][c0 + 2 * q + 1], h1, l1);
            hw[q] = pk(h0, h1); lw[q] = pk(l0, l1);
        }
        const long o = ((long)b * 256 + p0 + pr) * 256 + c0;
        *(uint4*)&ATh[o] = make_uint4(hw[0], hw[1], hw[2], hw[3]);
        *(uint4*)&ATl[o] = make_uint4(lw[0], lw[1], lw[2], lw[3]);
    }
    {
        uint32_t hw[4], lw[4];
#pragma unroll
        for (int q = 0; q < 4; q++) {
            __half h0, l0, h1, l1;
            split1(sm[2 * q][t], h0, l0); split1(sm[2 * q + 1][t], h1, l1);
            hw[q] = pk(h0, h1); lw[q] = pk(l0, l1);
        }
        const long o = ((long)b * 256 + t) * 256 + p0;
        *(uint4*)&TTh[o] = make_uint4(hw[0], hw[1], hw[2], hw[3]);
        *(uint4*)&TTl[o] = make_uint4(lw[0], lw[1], lw[2], lw[3]);
    }
}

__global__ __launch_bounds__(128) void mlp_layer_kernel(
    const float* __restrict__ A1, const float* __restrict__ A2, int ksplit,
    const float* __restrict__ W, const float* __restrict__ bias,
    float* __restrict__ out, int N, int K, int do_tanh)
{
    const int n = blockIdx.x * 128 + threadIdx.x;
    const int m0 = blockIdx.y * 8;
    __shared__ float As[8][129];
    float acc[8];
#pragma unroll
    for (int i = 0; i < 8; i++) acc[i] = 0.f;
    for (int k0 = 0; k0 < K; k0 += 128) {
#pragma unroll
        for (int i = 0; i < 8; i++) {
            const int k = k0 + threadIdx.x;
            As[i][threadIdx.x] = (k < ksplit)
                ? A1[(long)(m0 + i) * ksplit + k]
                : A2[(long)(m0 + i) * ksplit + (k - ksplit)];
        }
        __syncthreads();
        for (int kk = 0; kk < 128; kk++) {
            const float wv = W[(long)(k0 + kk) * N + n];
#pragma unroll
            for (int i = 0; i < 8; i++) acc[i] += As[i][kk] * wv;
        }
        __syncthreads();
    }
    const float bb = bias[n];
#pragma unroll
    for (int i = 0; i < 8; i++) {
        float r = acc[i] + bb;
        out[(long)(m0 + i) * N + n] = do_tanh ? tanhf(r) : r;
    }
}

__global__ void final_layer_kernel(
    const float* __restrict__ A, const float* __restrict__ W3,
    const float* __restrict__ b3, float* __restrict__ out)
{
    const int m = blockIdx.x / 3, n = blockIdx.x % 3, lane = threadIdx.x;
    float s = 0.f;
    for (int k = lane; k < 2048; k += 32)
        s += A[(long)m * 2048 + k] * W3[(long)k * 3 + n];
#pragma unroll
    for (int o = 16; o; o >>= 1) s += __shfl_xor_sync(0xffffffffu, s, o);
    if (lane == 0) out[m * 3 + n] = s + b3[n];
}

extern "C" void kernel_launch(void* const* d_in, const int* in_sizes, int n_in,
                              void* d_out, int out_size)
{
    const float* P   = (const float*)d_in[0];
    const float* Hy  = (const float*)d_in[1];
    const float* W_F = (const float*)d_in[2];
    const float* W_G = (const float*)d_in[3];
    const float* W1  = (const float*)d_in[4];
    const float* b1  = (const float*)d_in[5];
    const float* W2  = (const float*)d_in[6];
    const float* b2  = (const float*)d_in[7];
    const float* W3  = (const float*)d_in[8];
    const float* b3  = (const float*)d_in[9];
    float* out = (float*)d_out;

    __half* hf = nullptr;
    float* f32 = nullptr;
    cudaGetSymbolAddress((void**)&hf, g_hf);
    cudaGetSymbolAddress((void**)&f32, g_f32);

    const int SM = 3 * ST_SZ;  // 192KB dynamic
    cudaFuncSetAttribute(mm<0>, cudaFuncAttributeMaxDynamicSharedMemorySize, SM);
    cudaFuncSetAttribute(mm<1>, cudaFuncAttributeMaxDynamicSharedMemorySize, SM);
    cudaFuncSetAttribute(mm<2>, cudaFuncAttributeMaxDynamicSharedMemorySize, SM);
    cudaFuncSetAttribute(mm_compare, cudaFuncAttributeMaxDynamicSharedMemorySize, SM);

    float* E  = f32 + OF_E;
    float* S1 = f32 + OF_S1;
    float* S2 = f32 + OF_S2;
    float* a1 = f32 + OF_A1;
    float* a2 = f32 + OF_A2;

    // launch order: proj GEMM at index 3 (ncu -s 5 profiles this slot)
    pack_nat2<<<dim3(8192, 2), 256>>>(P, Hy, hf + O_PH_H, hf + O_PH_L,
                                      hf + O_HH_H, hf + O_HH_L, 2097152);       // 0
    pack_T<<<dim3(32, 32, 1), 256>>>(W_F, hf + O_WF_H, hf + O_WF_L, 1024, 1024); // 1
    pack_T<<<dim3(64, 64, 1), 256>>>(W_G, hf + O_WG_H, hf + O_WG_L, 2048, 2048); // 2

    // projections: Fp/Fh = tanh(X @ W_F). A [8192][1024], B = W_F^T [1024][1024]
    mm<2><<<dim3(8, 64, 1), 512, SM>>>(                                          // 3 <- ncu
        hf + O_PH_H, hf + O_PH_L, 1024, 0, hf + O_WF_H, hf + O_WF_L, 1024, 0,
        nullptr, 0, 0, hf + O_FP_H, hf + O_FP_L, 1024, 0, 1024);
    mm<2><<<dim3(8, 64, 1), 512, SM>>>(                                          // 4
        hf + O_HH_H, hf + O_HH_L, 1024, 0, hf + O_WF_H, hf + O_WF_L, 1024, 0,
        nullptr, 0, 0, hf + O_FH_H, hf + O_FH_L, 1024, 0, 1024);

    pack_T<<<dim3(32, 8, 32), 256>>>(P,  hf + O_PT_H, hf + O_PT_L, 256, 1024);   // 5
    pack_T<<<dim3(32, 8, 32), 256>>>(Hy, hf + O_HT_H, hf + O_HT_L, 256, 1024);   // 6

    // E[b] = Fp[b] @ Fh[b]^T
    mm<0><<<dim3(2, 2, 32), 512, SM>>>(
        hf + O_FP_H, hf + O_FP_L, 1024, 262144, hf + O_FH_H, hf + O_FH_L, 1024, 262144,
        E, 256, 65536, nullptr, nullptr, 0, 0, 1024);

    softmax_pack<<<1024, dim3(32, 8)>>>(E, hf + O_AT_H, hf + O_AT_L, hf + O_TT_H, hf + O_TT_L);

    // betas = attn @ H (B = H^T) ; alphas = attn^T @ P (B = P^T)
    mm<1><<<dim3(8, 2, 32), 512, SM>>>(
        hf + O_AT_H, hf + O_AT_L, 256, 65536, hf + O_HT_H, hf + O_HT_L, 256, 262144,
        nullptr, 0, 0, hf + O_BE_H, hf + O_BE_L, 1024, 262144, 256);
    mm<1><<<dim3(8, 2, 32), 512, SM>>>(
        hf + O_TT_H, hf + O_TT_L, 256, 65536, hf + O_PT_H, hf + O_PT_L, 256, 262144,
        nullptr, 0, 0, hf + O_AL_H, hf + O_AL_L, 1024, 262144, 256);

    // compare (fused GEMM + tanh + sequence-sum)
    mm_compare<<<dim3(16, 1, 32), 512, SM>>>(
        hf + O_PH_H, hf + O_PH_L, hf + O_BE_H, hf + O_BE_L, hf + O_WG_H, hf + O_WG_L, S1);
    mm_compare<<<dim3(16, 1, 32), 512, SM>>>(
        hf + O_HH_H, hf + O_HH_L, hf + O_AL_H, hf + O_AL_L, hf + O_WG_H, hf + O_WG_L, S2);

    // classifier
    mlp_layer_kernel<<<dim3(16, 4), 128>>>(S1, S2, 2048, W1, b1, a1, 2048, 4096, 1);
    mlp_layer_kernel<<<dim3(16, 4), 128>>>(a1, a1, 2048, W2, b2, a2, 2048, 2048, 1);
    final_layer_kernel<<<96, 32>>>(a2, W3, b3, out);
}

// round 14
// speedup vs baseline: 1.0896x; 1.0574x over previous
#include <cuda_runtime.h>
#include <cuda_fp16.h>
#include <math.h>
#include <stdint.h>

// ---------------------------------------------------------------------------
// Decomposable-Attention NLI forward. mma.sync fp16 hi/lo-split (3 products).
// 128x64 block tile, 256 threads (8 warps 4x2, 32x32 warp tile), 2 CTAs/SM,
// hoisted ldmatrix addresses, 2-stage cp.async ring, fused launches.
// B=32, L=256, D=1024, FF=2048.
// ---------------------------------------------------------------------------

// fp16 scratch offsets (elements)
#define O_PH_H 0L
#define O_PH_L 8388608L
#define O_HH_H 16777216L
#define O_HH_L 25165824L
#define O_FP_H 33554432L
#define O_FP_L 41943040L
#define O_FH_H 50331648L
#define O_FH_L 58720256L
#define O_PT_H 67108864L
#define O_PT_L 75497472L
#define O_HT_H 83886080L
#define O_HT_L 92274688L
#define O_BE_H 100663296L
#define O_BE_L 109051904L
#define O_AL_H 117440512L
#define O_AL_L 125829120L
#define O_WF_H 134217728L
#define O_WF_L 135266304L
#define O_WG_H 136314880L
#define O_WG_L 140509184L
#define O_AT_H 144703488L
#define O_AT_L 146800640L
#define O_TT_H 148897792L
#define O_TT_L 150994944L
#define BF_TOTAL 153092096L
#define OF_E  0L
#define OF_S1 2097152L
#define OF_S2 2162688L
#define OF_A1 2228224L
#define OF_A2 2293760L
#define F32_TOTAL 2359296L

__device__ __align__(1024) __half g_hf[BF_TOTAL];
__device__ __align__(1024) float g_f32[F32_TOTAL];

// stage layout (bytes): Ah 16K | Al 16K | Bh 8K | Bl 8K = 48KB; 2 stages
#define ST_AL 16384
#define ST_BH 32768
#define ST_BL 40960
#define ST_SZ 49152

__device__ __forceinline__ uint32_t smem_u32(const void* p) {
    uint32_t a;
    asm("{ .reg .u64 t; cvta.to.shared.u64 t, %1; cvt.u32.u64 %0, t; }" : "=r"(a) : "l"(p));
    return a;
}
__device__ __forceinline__ void split1(float v, __half& h, __half& l) {
    h = __float2half_rn(v);
    l = __float2half_rn(v - __half2float(h));
}
__device__ __forceinline__ uint32_t pk(__half a, __half b) {
    return (uint32_t)__half_as_ushort(a) | ((uint32_t)__half_as_ushort(b) << 16);
}
__device__ __forceinline__ void mma_f16(float* c, const uint32_t* a, const uint32_t* b) {
    asm volatile(
        "mma.sync.aligned.m16n8k16.row.col.f32.f16.f16.f32 "
        "{%0,%1,%2,%3},{%4,%5,%6,%7},{%8,%9},{%0,%1,%2,%3};\n"
        : "+f"(c[0]), "+f"(c[1]), "+f"(c[2]), "+f"(c[3])
        : "r"(a[0]), "r"(a[1]), "r"(a[2]), "r"(a[3]), "r"(b[0]), "r"(b[1]));
}
__device__ __forceinline__ void ldsm4(uint32_t* r, uint32_t addr) {
    asm volatile("ldmatrix.sync.aligned.m8n8.x4.shared.b16 {%0,%1,%2,%3}, [%4];"
                 : "=r"(r[0]), "=r"(r[1]), "=r"(r[2]), "=r"(r[3]) : "r"(addr));
}

// cp.async a ROWS x 64-fp16(128B) SW128 tile; 256 threads
template <int ROWS>
__device__ __forceinline__ void ld_sw128(uint32_t sb, const __half* g, long ld, int t) {
    constexpr int ITERS = ROWS * 8 / 256;
#pragma unroll
    for (int i = 0; i < ITERS; i++) {
        const int idx = t + i * 256;
        const int r = idx >> 3, c = idx & 7;
        uint32_t dst = sb + r * 128 + ((c ^ (r & 7)) << 4);
        asm volatile("cp.async.cg.shared.global [%0], [%1], 16;"
                     :: "r"(dst), "l"(g + (long)r * ld + c * 8) : "memory");
    }
}

// Precompute the 16 stage-relative ldmatrix offsets for this warp.
__device__ __forceinline__ void mk_addrs(uint32_t aA[2][4], uint32_t aB[2][4],
                                         int wm, int wn, int lane) {
    const int lm = lane & 7, mat = lane >> 3;
    const int rsel = (mat & 1) * 8 + lm;
    const int csel = mat >> 1;
#pragma unroll
    for (int s = 0; s < 4; s++) {
        const int ch = 2 * s + csel;
#pragma unroll
        for (int mf = 0; mf < 2; mf++) {
            const int rm = wm * 32 + mf * 16 + rsel;
            aA[mf][s] = rm * 128 + ((ch ^ (rm & 7)) << 4);
        }
#pragma unroll
        for (int nfp = 0; nfp < 2; nfp++) {
            const int rn = wn * 32 + nfp * 16 + rsel;
            aB[nfp][s] = rn * 128 + ((ch ^ (rn & 7)) << 4);
        }
    }
}

// warp compute over one K64 stage, hoisted addresses, product-major order.
__device__ __forceinline__ void wcompute(uint32_t sb, const uint32_t aA[2][4],
                                         const uint32_t aB[2][4], float acc[2][4][4]) {
#pragma unroll
    for (int s = 0; s < 4; s++) {
        uint32_t bh[4][2], bl[4][2];
#pragma unroll
        for (int nfp = 0; nfp < 2; nfp++) {
            uint32_t q[4];
            ldsm4(q, sb + ST_BH + aB[nfp][s]);
            bh[nfp * 2][0] = q[0]; bh[nfp * 2 + 1][0] = q[1];
            bh[nfp * 2][1] = q[2]; bh[nfp * 2 + 1][1] = q[3];
            ldsm4(q, sb + ST_BL + aB[nfp][s]);
            bl[nfp * 2][0] = q[0]; bl[nfp * 2 + 1][0] = q[1];
            bl[nfp * 2][1] = q[2]; bl[nfp * 2 + 1][1] = q[3];
        }
        uint32_t ah[2][4], al[2][4];
#pragma unroll
        for (int mf = 0; mf < 2; mf++) {
            ldsm4(ah[mf], sb + aA[mf][s]);
            ldsm4(al[mf], sb + ST_AL + aA[mf][s]);
        }
#pragma unroll
        for (int mf = 0; mf < 2; mf++)
#pragma unroll
            for (int nf = 0; nf < 4; nf++) mma_f16(acc[mf][nf], ah[mf], bh[nf]);
#pragma unroll
        for (int mf = 0; mf < 2; mf++)
#pragma unroll
            for (int nf = 0; nf < 4; nf++) mma_f16(acc[mf][nf], ah[mf], bl[nf]);
#pragma unroll
        for (int mf = 0; mf < 2; mf++)
#pragma unroll
            for (int nf = 0; nf < 4; nf++) mma_f16(acc[mf][nf], al[mf], bh[nf]);
    }
}

// ---------------------------------------------------------------------------
// D = A @ B^T. A[m][k], B[n][k] fp16 h/l row-major. Block tile 128x64,
// 256 threads (8 warps 4x2), 2-stage ring, 2 CTAs/SM.
// EPI: 0 = fp32 store; 1 = hi/lo pack store; 2 = tanh + pack store.
// ---------------------------------------------------------------------------
template <int EPI>
__global__ __launch_bounds__(256, 2) void mm(
    const __half* __restrict__ Ah, const __half* __restrict__ Al, long lda, long sA,
    const __half* __restrict__ Bh, const __half* __restrict__ Bl, long ldb, long sB,
    float* __restrict__ Cf, long ldc, long sC,
    __half* __restrict__ Oh, __half* __restrict__ Ol, long ldo, long sO, int K)
{
    extern __shared__ __align__(16) char dsm[];
    const uint32_t base = smem_u32(dsm);
    const int t = threadIdx.x, lane = t & 31, wid = t >> 5;
    const int wm = wid >> 1, wn = wid & 1;
    const int bm = blockIdx.y * 128, bn = blockIdx.x * 64, z = blockIdx.z;

    const __half* Azh = Ah + z * sA + (long)bm * lda;
    const __half* Azl = Al + z * sA + (long)bm * lda;
    const __half* Bzh = Bh + z * sB + (long)bn * ldb;
    const __half* Bzl = Bl + z * sB + (long)bn * ldb;
    const int ns = K >> 6;

    uint32_t aA[2][4], aB[2][4];
    mk_addrs(aA, aB, wm, wn, lane);

    float acc[2][4][4];
#pragma unroll
    for (int i = 0; i < 2; i++)
#pragma unroll
        for (int j = 0; j < 4; j++)
#pragma unroll
            for (int q = 0; q < 4; q++) acc[i][j][q] = 0.f;

    auto issue = [&](int j) {
        const uint32_t sb = base + (j & 1) * ST_SZ;
        const long ko = (long)j << 6;
        ld_sw128<128>(sb,         Azh + ko, lda, t);
        ld_sw128<128>(sb + ST_AL, Azl + ko, lda, t);
        ld_sw128<64>(sb + ST_BH,  Bzh + ko, ldb, t);
        ld_sw128<64>(sb + ST_BL,  Bzl + ko, ldb, t);
        asm volatile("cp.async.commit_group;" ::: "memory");
    };

    issue(0);
    for (int j = 0; j < ns; j++) {
        if (j + 1 < ns) {
            issue(j + 1);
            asm volatile("cp.async.wait_group 1;" ::: "memory");
        } else {
            asm volatile("cp.async.wait_group 0;" ::: "memory");
        }
        __syncthreads();
        wcompute(base + (j & 1) * ST_SZ, aA, aB, acc);
        __syncthreads();
    }

    const int r = lane >> 2, c2 = (lane & 3) * 2;
#pragma unroll
    for (int mf = 0; mf < 2; mf++)
#pragma unroll
        for (int nf = 0; nf < 4; nf++) {
            const int row = bm + wm * 32 + mf * 16 + r;
            const int col = bn + wn * 32 + nf * 8 + c2;
            float v0 = acc[mf][nf][0], v1 = acc[mf][nf][1];
            float v2 = acc[mf][nf][2], v3 = acc[mf][nf][3];
            if (EPI == 2) { v0 = tanhf(v0); v1 = tanhf(v1); v2 = tanhf(v2); v3 = tanhf(v3); }
            if (EPI == 0) {
                *(float2*)&Cf[z * sC + (long)row * ldc + col] = make_float2(v0, v1);
                *(float2*)&Cf[z * sC + (long)(row + 8) * ldc + col] = make_float2(v2, v3);
            } else {
                __half h0, l0, h1, l1;
                split1(v0, h0, l0); split1(v1, h1, l1);
                const long o0 = z * sO + (long)row * ldo + col;
                *(uint32_t*)&Oh[o0] = pk(h0, h1);
                *(uint32_t*)&Ol[o0] = pk(l0, l1);
                split1(v2, h0, l0); split1(v3, h1, l1);
                const long o1 = z * sO + (long)(row + 8) * ldo + col;
                *(uint32_t*)&Oh[o1] = pk(h0, h1);
                *(uint32_t*)&Ol[o1] = pk(l0, l1);
            }
        }
}

// ---------------------------------------------------------------------------
// Fused compare (S1+S2 in one launch, z in [0,64)):
// half = z>>5 selects (X1,X2,S); S[zz,n] = sum_p tanh(concat(X1,X2)[zz,p,:] @ W[:,n])
// ---------------------------------------------------------------------------
__global__ __launch_bounds__(256, 2) void mm_compare(
    const __half* __restrict__ P1h, const __half* __restrict__ P1l,
    const __half* __restrict__ P2h, const __half* __restrict__ P2l,
    const __half* __restrict__ Q1h, const __half* __restrict__ Q1l,
    const __half* __restrict__ Q2h, const __half* __restrict__ Q2l,
    const __half* __restrict__ Wh,  const __half* __restrict__ Wl,
    float* __restrict__ S1, float* __restrict__ S2)
{
    extern __shared__ __align__(16) char dsm[];
    __shared__ float red[4][64];
    const uint32_t base = smem_u32(dsm);
    const int t = threadIdx.x, lane = t & 31, wid = t >> 5;
    const int wm = wid >> 1, wn = wid & 1;
    const int bn = blockIdx.x * 64;
    const int half = blockIdx.z >> 5, z = blockIdx.z & 31;

    const __half* X1h = half ? P2h : P1h;
    const __half* X1l = half ? P2l : P1l;
    const __half* X2h = half ? Q2h : Q1h;
    const __half* X2l = half ? Q2l : Q1l;
    float* S = half ? S2 : S1;

    const __half* Wbh = Wh + (long)bn * 2048;
    const __half* Wbl = Wl + (long)bn * 2048;

    uint32_t aA[2][4], aB[2][4];
    mk_addrs(aA, aB, wm, wn, lane);

    float csum[4][2];
#pragma unroll
    for (int nf = 0; nf < 4; nf++) { csum[nf][0] = 0.f; csum[nf][1] = 0.f; }

    for (int mt = 0; mt < 2; mt++) {
        float acc[2][4][4];
#pragma unroll
        for (int i = 0; i < 2; i++)
#pragma unroll
            for (int j = 0; j < 4; j++)
#pragma unroll
                for (int q = 0; q < 4; q++) acc[i][j][q] = 0.f;

        auto issue = [&](int j) {
            const uint32_t sb = base + (j & 1) * ST_SZ;
            const long ro = (long)z * 262144 + (long)mt * 131072;
            const __half* axh = (j < 16) ? X1h + ro + ((long)j << 6)
                                         : X2h + ro + ((long)(j - 16) << 6);
            const __half* axl = (j < 16) ? X1l + ro + ((long)j << 6)
                                         : X2l + ro + ((long)(j - 16) << 6);
            ld_sw128<128>(sb,         axh, 1024, t);
            ld_sw128<128>(sb + ST_AL, axl, 1024, t);
            ld_sw128<64>(sb + ST_BH,  Wbh + ((long)j << 6), 2048, t);
            ld_sw128<64>(sb + ST_BL,  Wbl + ((long)j << 6), 2048, t);
            asm volatile("cp.async.commit_group;" ::: "memory");
        };

        issue(0);
        for (int j = 0; j < 32; j++) {
            if (j + 1 < 32) {
                issue(j + 1);
                asm volatile("cp.async.wait_group 1;" ::: "memory");
            } else {
                asm volatile("cp.async.wait_group 0;" ::: "memory");
            }
            __syncthreads();
            wcompute(base + (j & 1) * ST_SZ, aA, aB, acc);
            __syncthreads();
        }
#pragma unroll
        for (int mf = 0; mf < 2; mf++)
#pragma unroll
            for (int nf = 0; nf < 4; nf++) {
                csum[nf][0] += tanhf(acc[mf][nf][0]) + tanhf(acc[mf][nf][2]);
                csum[nf][1] += tanhf(acc[mf][nf][1]) + tanhf(acc[mf][nf][3]);
            }
    }

    // reduce the 8 row-groups within the warp (lanes sharing lane&3)
#pragma unroll
    for (int off = 4; off <= 16; off <<= 1)
#pragma unroll
        for (int nf = 0; nf < 4; nf++) {
            csum[nf][0] += __shfl_xor_sync(0xffffffffu, csum[nf][0], off);
            csum[nf][1] += __shfl_xor_sync(0xffffffffu, csum[nf][1], off);
        }
    if (lane < 4) {
#pragma unroll
        for (int nf = 0; nf < 4; nf++) {
            red[wm][wn * 32 + nf * 8 + 2 * lane + 0] = csum[nf][0];
            red[wm][wn * 32 + nf * 8 + 2 * lane + 1] = csum[nf][1];
        }
    }
    __syncthreads();
    if (t < 64)
        S[(long)z * 2048 + bn + t] = red[0][t] + red[1][t] + red[2][t] + red[3][t];
}

// fp32 row-major -> elementwise fp16 hi/lo (same layout); two tensors via grid.y
__global__ __launch_bounds__(256) void pack_nat2(
    const float* __restrict__ X0, const float* __restrict__ X1,
    __half* __restrict__ H0, __half* __restrict__ L0,
    __half* __restrict__ H1, __half* __restrict__ L1, long n4)
{
    const long i = (long)blockIdx.x * 256 + threadIdx.x;
    if (i >= n4) return;
    const float* X = blockIdx.y ? X1 : X0;
    __half* H = blockIdx.y ? H1 : H0;
    __half* L = blockIdx.y ? L1 : L0;
    float4 v = ((const float4*)X)[i];
    __half h[4], l[4];
    split1(v.x, h[0], l[0]); split1(v.y, h[1], l[1]);
    split1(v.z, h[2], l[2]); split1(v.w, h[3], l[3]);
    ((uint2*)H)[i] = make_uint2(pk(h[0], h[1]), pk(h[2], h[3]));
    ((uint2*)L)[i] = make_uint2(pk(l[0], l[1]), pk(l[2], l[3]));
}

// fp32 [Z][R][C] -> fp16 hi/lo [Z][C][R]
__global__ __launch_bounds__(256) void pack_T(
    const float* __restrict__ X, __half* __restrict__ H,
    __half* __restrict__ L, int R, int C)
{
    __shared__ float tile[32][33];
    const int c0 = blockIdx.x * 32, r0 = blockIdx.y * 32;
    const int tx = threadIdx.x & 31, ty = threadIdx.x >> 5;
    const long zoff = (long)blockIdx.z * R * C;
#pragma unroll
    for (int i = 0; i < 4; i++)
        tile[ty + i * 8][tx] = X[zoff + (long)(r0 + ty + i * 8) * C + c0 + tx];
    __syncthreads();
#pragma unroll
    for (int i = 0; i < 4; i++) {
        const int c = ty + i * 8;
        __half h, l;
        split1(tile[tx][c], h, l);
        H[zoff + (long)(c0 + c) * R + r0 + tx] = h;
        L[zoff + (long)(c0 + c) * R + r0 + tx] = l;
    }
}

// softmax over 256 cols; writes attn [b][p][h] and attn^T [b][h][p] hi/lo
__global__ void softmax_pack(
    const float* __restrict__ E,
    __half* __restrict__ ATh, __half* __restrict__ ATl,
    __half* __restrict__ TTh, __half* __restrict__ TTl)
{
    __shared__ float sm[8][257];
    const int b = blockIdx.x >> 5;
    const int p0 = (blockIdx.x & 31) << 3;
    const int lane = threadIdx.x, ty = threadIdx.y;
    const float* row = E + ((long)b * 256 + p0 + ty) * 256;
    float v[8];
    float mx = -1e30f;
#pragma unroll
    for (int i = 0; i < 8; i++) { v[i] = row[i * 32 + lane]; mx = fmaxf(mx, v[i]); }
#pragma unroll
    for (int o = 16; o; o >>= 1) mx = fmaxf(mx, __shfl_xor_sync(0xffffffffu, mx, o));
    float s = 0.f;
#pragma unroll
    for (int i = 0; i < 8; i++) { v[i] = expf(v[i] - mx); s += v[i]; }
#pragma unroll
    for (int o = 16; o; o >>= 1) s += __shfl_xor_sync(0xffffffffu, s, o);
    const float inv = 1.0f / s;
#pragma unroll
    for (int i = 0; i < 8; i++) sm[ty][i * 32 + lane] = v[i] * inv;
    __syncthreads();
    const int t = ty * 32 + lane;
    {
        const int pr = t >> 5, c0 = (t & 31) << 3;
        uint32_t hw[4], lw[4];
#pragma unroll
        for (int q = 0; q < 4; q++) {
            __half h0, l0, h1, l1;
            split1(sm[pr][c0 + 2 * q], h0, l0); split1(sm[pr][c0 + 2 * q + 1], h1, l1);
            hw[q] = pk(h0, h1); lw[q] = pk(l0, l1);
        }
        const long o = ((long)b * 256 + p0 + pr) * 256 + c0;
        *(uint4*)&ATh[o] = make_uint4(hw[0], hw[1], hw[2], hw[3]);
        *(uint4*)&ATl[o] = make_uint4(lw[0], lw[1], lw[2], lw[3]);
    }
    {
        uint32_t hw[4], lw[4];
#pragma unroll
        for (int q = 0; q < 4; q++) {
            __half h0, l0, h1, l1;
            split1(sm[2 * q][t], h0, l0); split1(sm[2 * q + 1][t], h1, l1);
            hw[q] = pk(h0, h1); lw[q] = pk(l0, l1);
        }
        const long o = ((long)b * 256 + t) * 256 + p0;
        *(uint4*)&TTh[o] = make_uint4(hw[0], hw[1], hw[2], hw[3]);
        *(uint4*)&TTl[o] = make_uint4(lw[0], lw[1], lw[2], lw[3]);
    }
}

__global__ __launch_bounds__(128) void mlp_layer_kernel(
    const float* __restrict__ A1, const float* __restrict__ A2, int ksplit,
    const float* __restrict__ W, const float* __restrict__ bias,
    float* __restrict__ out, int N, int K, int do_tanh)
{
    const int n = blockIdx.x * 128 + threadIdx.x;
    const int m0 = blockIdx.y * 8;
    __shared__ float As[8][129];
    float acc[8];
#pragma unroll
    for (int i = 0; i < 8; i++) acc[i] = 0.f;
    for (int k0 = 0; k0 < K; k0 += 128) {
#pragma unroll
        for (int i = 0; i < 8; i++) {
            const int k = k0 + threadIdx.x;
            As[i][threadIdx.x] = (k < ksplit)
                ? A1[(long)(m0 + i) * ksplit + k]
                : A2[(long)(m0 + i) * ksplit + (k - ksplit)];
        }
        __syncthreads();
        for (int kk = 0; kk < 128; kk++) {
            const float wv = W[(long)(k0 + kk) * N + n];
#pragma unroll
            for (int i = 0; i < 8; i++) acc[i] += As[i][kk] * wv;
        }
        __syncthreads();
    }
    const float bb = bias[n];
#pragma unroll
    for (int i = 0; i < 8; i++) {
        float r = acc[i] + bb;
        out[(long)(m0 + i) * N + n] = do_tanh ? tanhf(r) : r;
    }
}

__global__ void final_layer_kernel(
    const float* __restrict__ A, const float* __restrict__ W3,
    const float* __restrict__ b3, float* __restrict__ out)
{
    const int m = blockIdx.x / 3, n = blockIdx.x % 3, lane = threadIdx.x;
    float s = 0.f;
    for (int k = lane; k < 2048; k += 32)
        s += A[(long)m * 2048 + k] * W3[(long)k * 3 + n];
#pragma unroll
    for (int o = 16; o; o >>= 1) s += __shfl_xor_sync(0xffffffffu, s, o);
    if (lane == 0) out[m * 3 + n] = s + b3[n];
}

extern "C" void kernel_launch(void* const* d_in, const int* in_sizes, int n_in,
                              void* d_out, int out_size)
{
    const float* P   = (const float*)d_in[0];
    const float* Hy  = (const float*)d_in[1];
    const float* W_F = (const float*)d_in[2];
    const float* W_G = (const float*)d_in[3];
    const float* W1  = (const float*)d_in[4];
    const float* b1  = (const float*)d_in[5];
    const float* W2  = (const float*)d_in[6];
    const float* b2  = (const float*)d_in[7];
    const float* W3  = (const float*)d_in[8];
    const float* b3  = (const float*)d_in[9];
    float* out = (float*)d_out;

    __half* hf = nullptr;
    float* f32 = nullptr;
    cudaGetSymbolAddress((void**)&hf, g_hf);
    cudaGetSymbolAddress((void**)&f32, g_f32);

    const int SM = 2 * ST_SZ;  // 96KB dynamic -> 2 CTAs/SM
    cudaFuncSetAttribute(mm<0>, cudaFuncAttributeMaxDynamicSharedMemorySize, SM);
    cudaFuncSetAttribute(mm<1>, cudaFuncAttributeMaxDynamicSharedMemorySize, SM);
    cudaFuncSetAttribute(mm<2>, cudaFuncAttributeMaxDynamicSharedMemorySize, SM);
    cudaFuncSetAttribute(mm_compare, cudaFuncAttributeMaxDynamicSharedMemorySize, SM);

    float* E  = f32 + OF_E;
    float* S1 = f32 + OF_S1;
    float* S2 = f32 + OF_S2;
    float* a1 = f32 + OF_A1;
    float* a2 = f32 + OF_A2;

    pack_nat2<<<dim3(8192, 2), 256>>>(P, Hy, hf + O_PH_H, hf + O_PH_L,
                                      hf + O_HH_H, hf + O_HH_L, 2097152);        // 0
    pack_T<<<dim3(32, 32, 1), 256>>>(W_F, hf + O_WF_H, hf + O_WF_L, 1024, 1024); // 1
    pack_T<<<dim3(64, 64, 1), 256>>>(W_G, hf + O_WG_H, hf + O_WG_L, 2048, 2048); // 2

    // fused projections: z=0 -> P, z=1 -> H (batch stride = PH->HH offset)
    mm<2><<<dim3(16, 64, 2), 256, SM>>>(                                         // 3 <- ncu
        hf + O_PH_H, hf + O_PH_L, 1024, 16777216,
        hf + O_WF_H, hf + O_WF_L, 1024, 0,
        nullptr, 0, 0, hf + O_FP_H, hf + O_FP_L, 1024, 16777216, 1024);

    pack_T<<<dim3(32, 8, 32), 256>>>(P,  hf + O_PT_H, hf + O_PT_L, 256, 1024);   // 4
    pack_T<<<dim3(32, 8, 32), 256>>>(Hy, hf + O_HT_H, hf + O_HT_L, 256, 1024);   // 5

    // E[b] = Fp[b] @ Fh[b]^T
    mm<0><<<dim3(4, 2, 32), 256, SM>>>(
        hf + O_FP_H, hf + O_FP_L, 1024, 262144, hf + O_FH_H, hf + O_FH_L, 1024, 262144,
        E, 256, 65536, nullptr, nullptr, 0, 0, 1024);

    softmax_pack<<<1024, dim3(32, 8)>>>(E, hf + O_AT_H, hf + O_AT_L, hf + O_TT_H, hf + O_TT_L);

    // betas = attn @ H (B = H^T, ldb = 256!) ; alphas = attn^T @ P (B = P^T)
    mm<1><<<dim3(16, 2, 32), 256, SM>>>(
        hf + O_AT_H, hf + O_AT_L, 256, 65536, hf + O_HT_H, hf + O_HT_L, 256, 262144,
        nullptr, 0, 0, hf + O_BE_H, hf + O_BE_L, 1024, 262144, 256);
    mm<1><<<dim3(16, 2, 32), 256, SM>>>(
        hf + O_TT_H, hf + O_TT_L, 256, 65536, hf + O_PT_H, hf + O_PT_L, 256, 262144,
        nullptr, 0, 0, hf + O_AL_H, hf + O_AL_L, 1024, 262144, 256);

    // fused compare (S1: z<32, S2: z>=32)
    mm_compare<<<dim3(32, 1, 64), 256, SM>>>(
        hf + O_PH_H, hf + O_PH_L, hf + O_HH_H, hf + O_HH_L,
        hf + O_BE_H, hf + O_BE_L, hf + O_AL_H, hf + O_AL_L,
        hf + O_WG_H, hf + O_WG_L, S1, S2);

    // classifier
    mlp_layer_kernel<<<dim3(16, 4), 128>>>(S1, S2, 2048, W1, b1, a1, 2048, 4096, 1);
    mlp_layer_kernel<<<dim3(16, 4), 128>>>(a1, a1, 2048, W2, b2, a2, 2048, 2048, 1);
    final_layer_kernel<<<96, 32>>>(a2, W3, b3, out);
}